// round 9
// baseline (speedup 1.0000x reference)
#include <cuda_runtime.h>
#include <cstdint>

#define PI_F 3.14159265358979323846f

// Packed 4-bit species table (up to 131072 atoms)
__device__ __align__(16) unsigned g_pk[16384];

// ---------------------------------------------------------------------------
// Prep kernel: zero aev AND pack atomic_numbers into 4-bit nibbles.
// ---------------------------------------------------------------------------
__global__ void ani_prep_kernel(const int* __restrict__ an, int N, int PKW,
                                float4* __restrict__ aevv, long long aev_v4)
{
    long long t = (long long)blockIdx.x * blockDim.x + threadIdx.x;
    const float4 z = make_float4(0.f, 0.f, 0.f, 0.f);
    for (long long v = t; v < aev_v4; v += (long long)gridDim.x * blockDim.x)
        aevv[v] = z;
    if (t < PKW) {
        int base = (int)t << 3;
        unsigned v = 0;
#pragma unroll
        for (int k = 0; k < 8; k++) {
            int a = base + k;
            unsigned s = (a < N) ? (unsigned)an[a] : 0u;
            v |= (s & 15u) << (k * 4);
        }
        g_pk[t] = v;
    }
}

// ---------------------------------------------------------------------------
// Radial kernel (standalone): 256 thr, 25KB smem table via cp.async.bulk,
// 8 blocks/SM (100% occ), 1024 pairs per block.
// ---------------------------------------------------------------------------
__global__ __launch_bounds__(256, 8)
void ani_radial_kernel(const float* __restrict__ r_ij,
                       const int*   __restrict__ pidx,
                       const int*   __restrict__ an,
                       float*       __restrict__ aev,
                       int P, int PKB)
{
    __shared__ __align__(128) unsigned spk[6272];      // 25088B table
    __shared__ __align__(8)   unsigned long long mbar;

    const int tid = threadIdx.x;
    const bool use_table = (PKB > 0);
    uint32_t mbar_a = (uint32_t)__cvta_generic_to_shared(&mbar);

    if (use_table) {
        if (tid == 0) {
            asm volatile("mbarrier.init.shared.b64 [%0], 1;" :: "r"(mbar_a) : "memory");
            asm volatile("fence.proxy.async.shared::cta;" ::: "memory");
        }
        __syncthreads();
        if (tid == 0) {
            uint32_t dst = (uint32_t)__cvta_generic_to_shared(spk);
            asm volatile("mbarrier.arrive.expect_tx.shared.b64 _, [%0], %1;"
                         :: "r"(mbar_a), "r"((unsigned)PKB) : "memory");
            asm volatile("cp.async.bulk.shared::cluster.global.mbarrier::complete_tx::bytes "
                         "[%0], [%1], %2, [%3];"
                         :: "r"(dst), "l"((const void*)g_pk), "r"((unsigned)PKB), "r"(mbar_a)
                         : "memory");
        }
    }

    // hoisted loads for all 4 iterations (latency overlaps the table copy)
    const int base = blockIdx.x * 1024;
    float d[4]; int pi[4], pj[4]; bool v[4];
#pragma unroll
    for (int it = 0; it < 4; it++) {
        int p = base + it * 256 + tid;
        v[it] = (p < P);
        d[it] = 0.f; pi[it] = 0; pj[it] = 0;
        if (v[it]) {
            d[it]  = __ldcs(r_ij + p);
            pi[it] = pidx[p];
            pj[it] = pidx[P + p];
        }
    }

    if (use_table) {
        unsigned done;
        do {
            asm volatile("{\n\t.reg .pred p;\n\t"
                         "mbarrier.try_wait.parity.shared.b64 p, [%1], 0;\n\t"
                         "selp.b32 %0, 1, 0, p;\n\t}"
                         : "=r"(done) : "r"(mbar_a) : "memory");
        } while (!done);
    }

#pragma unroll
    for (int it = 0; it < 4; it++) {
        if (!v[it]) continue;
        int i = pi[it], j = pj[it];
        int si, sj;
        if (use_table) {
            si = (spk[i >> 3] >> ((i & 7) * 4)) & 7;
            sj = (spk[j >> 3] >> ((j & 7) * 4)) & 7;
        } else {
            si = an[i];
            sj = an[j];
        }
        float dd0 = d[it];
        float fc = (dd0 <= 5.1f) ? (0.5f * __cosf((PI_F / 5.1f) * dd0) + 0.5f) : 0.0f;
        float f[8];
#pragma unroll
        for (int k = 0; k < 8; k++) {
            float dd = dd0 - (0.8f + 0.5375f * (float)k);   // ShfR[k]
            f[k] = 0.25f * __expf(-19.7f * dd * dd) * fc;
        }
        float4 lo = make_float4(f[0], f[1], f[2], f[3]);
        float4 hi = make_float4(f[4], f[5], f[6], f[7]);
        float4* rA = reinterpret_cast<float4*>(aev + (long long)(i * 7 + sj) * 8);
        float4* rB = reinterpret_cast<float4*>(aev + (long long)(j * 7 + si) * 8);
        atomicAdd(rA,     lo);
        atomicAdd(rA + 1, hi);
        atomicAdd(rB,     lo);
        atomicAdd(rB + 1, hi);
    }
}

// ---------------------------------------------------------------------------
// Angular kernel (standalone, proven R2 config: 128 thr, 18.4KB stage).
// ---------------------------------------------------------------------------
__global__ __launch_bounds__(128)
void ani_angular_kernel(const float* __restrict__ vec12,
                        float*       __restrict__ ang,
                        int T)
{
    __shared__ float s[128][36];   // 144B rows: 16B-aligned, conflict-free

    const int tid = threadIdx.x;
    const long long t = (long long)blockIdx.x * 128 + tid;

    float out[32];

    if (t < T) {
        const float* v1 = vec12 + 3LL * t;
        const float* v2 = vec12 + 3LL * T + 3LL * t;
        float x1 = __ldcs(v1 + 0), y1 = __ldcs(v1 + 1), z1 = __ldcs(v1 + 2);
        float x2 = __ldcs(v2 + 0), y2 = __ldcs(v2 + 1), z2 = __ldcs(v2 + 2);

        float d11 = fmaf(x1, x1, fmaf(y1, y1, z1 * z1));
        float d22 = fmaf(x2, x2, fmaf(y2, y2, z2 * z2));
        float d12 = fmaf(x1, x2, fmaf(y1, y2, z1 * z2));

        float rs1 = rsqrtf(d11);
        float rs2 = rsqrtf(d22);
        float d1  = d11 * rs1;
        float d2  = d22 * rs2;

        float cost = 0.95f * d12 * rs1 * rs2;                 // |cost| <= 0.95
        float sint = sqrtf(fmaxf(1.0f - cost * cost, 0.0f));  // theta in [0,pi]

        float fc1 = (d1 <= 3.5f) ? (0.5f * __cosf((PI_F / 3.5f) * d1) + 0.5f) : 0.0f;
        float fc2 = (d2 <= 3.5f) ? (0.5f * __cosf((PI_F / 3.5f) * d2) + 0.5f) : 0.0f;
        float fc2x = 2.0f * fc1 * fc2;

        float u = 0.5f * (d1 + d2);
        float frad[8];
#pragma unroll
        for (int a = 0; a < 8; a++) {
            float dd = u - (0.8f + 0.3375f * (float)a);   // ShfA[a]
            frad[a] = __expf(-12.5f * dd * dd);
        }

        const float CZ[4] = { 0.9238795325f,  0.3826834324f, -0.3826834324f, -0.9238795325f };
        const float SZ[4] = { 0.3826834324f,  0.9238795325f,  0.9238795325f,  0.3826834324f };

#pragma unroll
        for (int z = 0; z < 4; z++) {
            float xz = 0.5f * (1.0f + cost * CZ[z] + sint * SZ[z]);   // in [0,1]
            float fang = (xz > 0.0f) ? __powf(xz, 14.1f) : 0.0f;
            fang *= fc2x;
#pragma unroll
            for (int a = 0; a < 8; a++)
                out[z * 8 + a] = fang * frad[a];
        }
    } else {
#pragma unroll
        for (int k = 0; k < 32; k++) out[k] = 0.0f;
    }

#pragma unroll
    for (int m = 0; m < 8; m++)
        *reinterpret_cast<float4*>(&s[tid][m * 4]) =
            *reinterpret_cast<const float4*>(&out[m * 4]);

    __syncthreads();

    const long long base  = (long long)blockIdx.x * (128 * 32);
    const long long limit = (long long)T * 32;
    float4* outv = reinterpret_cast<float4*>(ang + base);
#pragma unroll
    for (int j = tid; j < 128 * 8; j += 128) {
        if (base + (long long)j * 4 < limit) {
            int q = j >> 3;
            int k = (j & 7) << 2;
            __stcs(&outv[j], *reinterpret_cast<const float4*>(&s[q][k]));
        }
    }
}

// ---------------------------------------------------------------------------
// Launch: fork-join graph.
//   branch A (forked stream): angular kernel
//   branch B (main stream)  : prep (zero aev + pack species) -> radial kernel
// Falls back to sequential single-stream if the fork is not permitted.
// ---------------------------------------------------------------------------
extern "C" void kernel_launch(void* const* d_in, const int* in_sizes, int n_in,
                              void* d_out, int out_size)
{
    const float* r_ij  = (const float*)d_in[0];
    const int*   pidx  = (const int*)  d_in[1];
    const int*   an    = (const int*)  d_in[2];
    const float* vec12 = (const float*)d_in[3];

    const int P = in_sizes[0];
    const int T = in_sizes[3] / 6;
    const int N = in_sizes[2];
    const long long aev_elems = (long long)N * 7 * 8;

    float* aev = (float*)d_out;
    float* ang = aev + aev_elems;

    const int PKW = (N + 7) / 8;
    int PKB = ((PKW * 4) + 15) & ~15;
    if (PKB > 25088) PKB = 0;

    const int A  = (T + 127) / 128;       // angular blocks
    const int RG = (P + 1023) / 1024;     // radial blocks (1024 pairs each)

    // one-time host resources (host-side only; no device allocations)
    static cudaStream_t s2  = nullptr;
    static cudaEvent_t  evF = nullptr, evA = nullptr;
    static bool init_tried = false;
    if (!init_tried) {
        init_tried = true;
        if (cudaStreamCreateWithFlags(&s2, cudaStreamNonBlocking) != cudaSuccess) s2 = nullptr;
        if (cudaEventCreateWithFlags(&evF, cudaEventDisableTiming) != cudaSuccess) evF = nullptr;
        if (cudaEventCreateWithFlags(&evA, cudaEventDisableTiming) != cudaSuccess) evA = nullptr;
    }

    bool forked = false;
    if (s2 && evF && evA) {
        if (cudaEventRecord(evF, 0) == cudaSuccess &&
            cudaStreamWaitEvent(s2, evF, 0) == cudaSuccess)
            forked = true;
    }

    // branch A: angular (independent of aev/prep)
    cudaStream_t sa = forked ? s2 : (cudaStream_t)0;
    ani_angular_kernel<<<A, 128, 0, sa>>>(vec12, ang, T);
    if (forked) cudaEventRecord(evA, s2);

    // branch B: prep then radial on the main stream
    ani_prep_kernel<<<2048, 256>>>(an, N, (PKB > 0) ? (PKB / 4) : 0,
                                   (float4*)aev, aev_elems / 4);
    ani_radial_kernel<<<RG, 256>>>(r_ij, pidx, an, aev, P, PKB);

    // join
    if (forked) cudaStreamWaitEvent((cudaStream_t)0, evA, 0);
}

// round 10
// speedup vs baseline: 1.0662x; 1.0662x over previous
#include <cuda_runtime.h>
#include <cstdint>

#define PI_F 3.14159265358979323846f

// Packed 4-bit species table (up to 131072 atoms)
__device__ __align__(16) unsigned g_pk[16384];

// ---------------------------------------------------------------------------
// Prep kernel: zero aev AND pack atomic_numbers into 4-bit nibbles.
// ---------------------------------------------------------------------------
__global__ void ani_prep_kernel(const int* __restrict__ an, int N, int PKW,
                                float4* __restrict__ aevv, long long aev_v4)
{
    long long t = (long long)blockIdx.x * blockDim.x + threadIdx.x;
    const float4 z = make_float4(0.f, 0.f, 0.f, 0.f);
    for (long long v = t; v < aev_v4; v += (long long)gridDim.x * blockDim.x)
        aevv[v] = z;
    if (t < PKW) {
        int base = (int)t << 3;
        unsigned v = 0;
#pragma unroll
        for (int k = 0; k < 8; k++) {
            int a = base + k;
            unsigned s = (a < N) ? (unsigned)an[a] : 0u;
            v |= (s & 15u) << (k * 4);
        }
        g_pk[t] = v;
    }
}

// ---------------------------------------------------------------------------
// Main kernel: single wave, per-block roles.
//   b <  RB : radial-persistent  (25KB smem species table, grid-stride pairs)
//   b >= RB : angular-persistent (18.4KB stage buffer, grid-stride tiles)
// smem is a 25.2KB union -> ~7 blocks/SM; first RB bids land on distinct SMs,
// so every SM runs both roles concurrently for the whole kernel.
// ---------------------------------------------------------------------------
__global__ __launch_bounds__(256, 7)
void ani_main_kernel(const float* __restrict__ r_ij,
                     const int*   __restrict__ pidx,
                     const int*   __restrict__ an,
                     const float* __restrict__ vec12,
                     float*       __restrict__ aev,
                     float*       __restrict__ ang,
                     int P, int T, int PKB, int RB, int G)
{
    __shared__ __align__(128) unsigned char smraw[25216];

    const int tid = threadIdx.x;
    const int b   = blockIdx.x;

    if (b < RB) {
        // ===================== RADIAL (persistent) ========================
        unsigned* spk = reinterpret_cast<unsigned*>(smraw);
        unsigned long long* mb = reinterpret_cast<unsigned long long*>(smraw + 25088);
        const bool use_table = (PKB > 0);
        uint32_t mbar_a = (uint32_t)__cvta_generic_to_shared(mb);

        if (use_table) {
            if (tid == 0) {
                asm volatile("mbarrier.init.shared.b64 [%0], 1;" :: "r"(mbar_a) : "memory");
                asm volatile("fence.proxy.async.shared::cta;" ::: "memory");
            }
            __syncthreads();
            if (tid == 0) {
                uint32_t dst = (uint32_t)__cvta_generic_to_shared(spk);
                asm volatile("mbarrier.arrive.expect_tx.shared.b64 _, [%0], %1;"
                             :: "r"(mbar_a), "r"((unsigned)PKB) : "memory");
                asm volatile("cp.async.bulk.shared::cluster.global.mbarrier::complete_tx::bytes "
                             "[%0], [%1], %2, [%3];"
                             :: "r"(dst), "l"((const void*)g_pk), "r"((unsigned)PKB), "r"(mbar_a)
                             : "memory");
            }
            unsigned done;
            do {
                asm volatile("{\n\t.reg .pred p;\n\t"
                             "mbarrier.try_wait.parity.shared.b64 p, [%1], 0;\n\t"
                             "selp.b32 %0, 1, 0, p;\n\t}"
                             : "=r"(done) : "r"(mbar_a) : "memory");
            } while (!done);
        }

        const long long stride = (long long)RB * 256;
        for (long long base = (long long)b * 256; base < P; base += stride) {
            long long p = base + tid;
            if (p < P) {
                float d = __ldcs(r_ij + p);
                int   i = pidx[p];
                int   j = pidx[P + p];
                int si, sj;
                if (use_table) {
                    si = (spk[i >> 3] >> ((i & 7) * 4)) & 7;
                    sj = (spk[j >> 3] >> ((j & 7) * 4)) & 7;
                } else {
                    si = an[i];
                    sj = an[j];
                }
                float fc = (d <= 5.1f) ? (0.5f * __cosf((PI_F / 5.1f) * d) + 0.5f) : 0.0f;
                float f[8];
#pragma unroll
                for (int k = 0; k < 8; k++) {
                    float dd = d - (0.8f + 0.5375f * (float)k);   // ShfR[k]
                    f[k] = 0.25f * __expf(-19.7f * dd * dd) * fc;
                }
                float4 lo = make_float4(f[0], f[1], f[2], f[3]);
                float4 hi = make_float4(f[4], f[5], f[6], f[7]);
                float4* rA = reinterpret_cast<float4*>(aev + (long long)(i * 7 + sj) * 8);
                float4* rB = reinterpret_cast<float4*>(aev + (long long)(j * 7 + si) * 8);
                atomicAdd(rA,     lo);
                atomicAdd(rA + 1, hi);
                atomicAdd(rB,     lo);
                atomicAdd(rB + 1, hi);
            }
        }
    } else {
        // ==================== ANGULAR (persistent) ========================
        float* sf = reinterpret_cast<float*>(smraw);   // 128 rows x 36 floats

        const int nA = G - RB;
        const long long nTiles = ((long long)T + 255) / 256;
        const long long limit  = (long long)T * 32;

        const float CZ[4] = { 0.9238795325f,  0.3826834324f, -0.3826834324f, -0.9238795325f };
        const float SZ[4] = { 0.3826834324f,  0.9238795325f,  0.9238795325f,  0.3826834324f };

        for (long long tile = b - RB; tile < nTiles; tile += nA) {
            const long long t = tile * 256 + tid;
            const bool vt = (t < T);

            float cost = 0.f, sint = 0.f, fc2x = 0.f;
            float frad[8];
#pragma unroll
            for (int a = 0; a < 8; a++) frad[a] = 0.f;

            if (vt) {
                const float* v1 = vec12 + 3LL * t;
                const float* v2 = vec12 + 3LL * T + 3LL * t;
                float x1 = __ldcs(v1 + 0), y1 = __ldcs(v1 + 1), z1 = __ldcs(v1 + 2);
                float x2 = __ldcs(v2 + 0), y2 = __ldcs(v2 + 1), z2 = __ldcs(v2 + 2);

                float d11 = fmaf(x1, x1, fmaf(y1, y1, z1 * z1));
                float d22 = fmaf(x2, x2, fmaf(y2, y2, z2 * z2));
                float d12 = fmaf(x1, x2, fmaf(y1, y2, z1 * z2));

                float rs1 = rsqrtf(d11);
                float rs2 = rsqrtf(d22);
                float d1  = d11 * rs1;
                float d2  = d22 * rs2;

                cost = 0.95f * d12 * rs1 * rs2;                 // |cost| <= 0.95
                sint = sqrtf(fmaxf(1.0f - cost * cost, 0.0f));  // theta in [0,pi]

                float fc1 = (d1 <= 3.5f) ? (0.5f * __cosf((PI_F / 3.5f) * d1) + 0.5f) : 0.0f;
                float fc2 = (d2 <= 3.5f) ? (0.5f * __cosf((PI_F / 3.5f) * d2) + 0.5f) : 0.0f;
                fc2x = 2.0f * fc1 * fc2;

                float u = 0.5f * (d1 + d2);
#pragma unroll
                for (int a = 0; a < 8; a++) {
                    float dd = u - (0.8f + 0.3375f * (float)a);   // ShfA[a]
                    frad[a] = __expf(-12.5f * dd * dd);
                }
            }

            // two staging passes through the 128-row buffer
#pragma unroll
            for (int pass = 0; pass < 2; pass++) {
                if ((tid >> 7) == pass) {
                    int r = tid & 127;
#pragma unroll
                    for (int z = 0; z < 4; z++) {
                        float xz = 0.5f * (1.0f + cost * CZ[z] + sint * SZ[z]);
                        float fang = (xz > 0.0f) ? __powf(xz, 14.1f) : 0.0f;
                        fang *= fc2x;
                        float4 a0 = make_float4(fang * frad[0], fang * frad[1],
                                                fang * frad[2], fang * frad[3]);
                        float4 a1 = make_float4(fang * frad[4], fang * frad[5],
                                                fang * frad[6], fang * frad[7]);
                        *reinterpret_cast<float4*>(&sf[r * 36 + z * 8])     = a0;
                        *reinterpret_cast<float4*>(&sf[r * 36 + z * 8 + 4]) = a1;
                    }
                }
                __syncthreads();

                const long long base = (tile * 256 + pass * 128) * 32;
                if (base < limit) {
                    float4* outv = reinterpret_cast<float4*>(ang + base);
#pragma unroll
                    for (int it = 0; it < 4; it++) {
                        int jj = tid + it * 256;
                        if (base + (long long)jj * 4 < limit) {
                            int qr = jj >> 3;
                            int k  = (jj & 7) << 2;
                            __stcs(&outv[jj], *reinterpret_cast<const float4*>(&sf[qr * 36 + k]));
                        }
                    }
                }
                __syncthreads();
            }
        }
    }
}

// ---------------------------------------------------------------------------
// Inputs (metadata order): r_ij f32[P], pair_indices i32[2,P],
// atomic_numbers i32[N_ATOMS], vec12 f32[2,T,3].
// Output: aev f32[N_ATOMS*7, 8] followed by ang f32[T, 32].
// ---------------------------------------------------------------------------
extern "C" void kernel_launch(void* const* d_in, const int* in_sizes, int n_in,
                              void* d_out, int out_size)
{
    const float* r_ij  = (const float*)d_in[0];
    const int*   pidx  = (const int*)  d_in[1];
    const int*   an    = (const int*)  d_in[2];
    const float* vec12 = (const float*)d_in[3];

    const int P = in_sizes[0];
    const int T = in_sizes[3] / 6;
    const int N = in_sizes[2];
    const long long aev_elems = (long long)N * 7 * 8;

    float* aev = (float*)d_out;
    float* ang = aev + aev_elems;

    const int PKW = (N + 7) / 8;
    int PKB = ((PKW * 4) + 15) & ~15;
    if (PKB > 25088) PKB = 0;

    static int nsm = 0;
    if (nsm == 0) {
        if (cudaDeviceGetAttribute(&nsm, cudaDevAttrMultiProcessorCount, 0) != cudaSuccess
            || nsm <= 0)
            nsm = 148;
    }

    int RB = 2 * nsm;                 // radial blocks (~2 per SM)
    int G  = 7 * nsm;                 // one full wave at 7 blocks/SM
    // make sure every radial block has work, and angular blocks exist
    const int RTmax = (P + 255) / 256;
    if (RB > RTmax) RB = (RTmax > 0) ? RTmax : 1;
    if (G <= RB) G = RB + 1;

    // zero aev + pack species
    ani_prep_kernel<<<2048, 256>>>(an, N, (PKB > 0) ? (PKB / 4) : 0,
                                   (float4*)aev, aev_elems / 4);

    ani_main_kernel<<<G, 256>>>(r_ij, pidx, an, vec12, aev, ang, P, T, PKB, RB, G);
}